// round 5
// baseline (speedup 1.0000x reference)
#include <cuda_runtime.h>
#include <math.h>

// Problem dims
#define Bsz 256
#define Tt  32
#define Ssz 2048
#define Asz 64
#define Psz 128
#define KAP 192          // A + P
#define SAP 2240         // S + A + P  (fc_W row stride)
#define S4  8192         // 4*S

// ---- scratch (device globals: allocation-free rule) ----
__device__ float g_h   [Bsz * Ssz];       // carry hidden
__device__ float g_c   [Bsz * Ssz];       // carry cell
__device__ float g_x1  [Bsz * Ssz];
__device__ float g_x2  [Bsz * Ssz];
__device__ float g_cc  [Bsz * S4];
__device__ float g_hn  [Bsz * Ssz];       // h_next
__device__ float g_base[Tt * Bsz * Ssz];  // per-step act/latent/bias contribution of fc
__device__ float g_eff [Ssz * Ssz];       // fc1_W[:, :S] + fc1_W[:, S:]
__device__ float g_al  [Tt * Bsz * KAP];  // packed [act_t, latent] rows

// ---------------------------------------------------------------------------
// Double-buffered tiled fp32 GEMM:  C[m,n] = epilogue( sum_k A[m,k] * W[n,k] )
// A: [M,K] row-major (lda), W: [N,K] row-major (ldw), C: [M,N] (ldc == N)
// MODE 0: relu(acc)
// MODE 1: relu(acc + extra[m*N + n]); optional duplicate store to C2
// MODE 2: acc + extra[n]              (bias, no relu)
// Requires M%64==0, N%64==0, K%16==0 (all shapes here satisfy this).
// ---------------------------------------------------------------------------
#define BM 64
#define BN 64
#define BK 16

template <int MODE>
__global__ __launch_bounds__(256, 2) void gemm_k(
    const float* __restrict__ A, int lda,
    const float* __restrict__ W, int ldw,
    float* __restrict__ C,
    const float* __restrict__ extra,
    float* __restrict__ C2,
    int N, int K)
{
    __shared__ float As[2][BK][BM + 8];
    __shared__ float Ws[2][BK][BN + 8];

    const int bm  = blockIdx.y * BM;
    const int bn  = blockIdx.x * BN;
    const int tid = threadIdx.x;

    // loader mapping: 256 threads, one float4 of A-tile and one of W-tile each
    const int lrow = tid >> 2;          // 0..63
    const int lk   = (tid & 3) << 2;    // 0,4,8,12

    // compute mapping: 16x16 threads, 4x4 outputs each
    const int ty = tid >> 4;
    const int tx = tid & 15;

    const float* Ap = A + (size_t)(bm + lrow) * lda + lk;
    const float* Wp = W + (size_t)(bn + lrow) * ldw + lk;

    float acc[4][4] = {};

    // ---- prologue: load K-slice 0 into buffer 0 ----
    {
        float4 av = *(const float4*)(Ap);
        float4 wv = *(const float4*)(Wp);
        As[0][lk + 0][lrow] = av.x; As[0][lk + 1][lrow] = av.y;
        As[0][lk + 2][lrow] = av.z; As[0][lk + 3][lrow] = av.w;
        Ws[0][lk + 0][lrow] = wv.x; Ws[0][lk + 1][lrow] = wv.y;
        Ws[0][lk + 2][lrow] = wv.z; Ws[0][lk + 3][lrow] = wv.w;
    }
    __syncthreads();

    int buf = 0;
    for (int k0 = BK; k0 < K; k0 += BK) {
        // prefetch next slice into registers (overlaps with FMAs below)
        float4 av = *(const float4*)(Ap + k0);
        float4 wv = *(const float4*)(Wp + k0);

        // compute on current buffer
#pragma unroll
        for (int kk = 0; kk < BK; kk++) {
            float4 a = *(const float4*)&As[buf][kk][ty << 2];
            float4 w = *(const float4*)&Ws[buf][kk][tx << 2];
            float ar[4] = {a.x, a.y, a.z, a.w};
            float wr[4] = {w.x, w.y, w.z, w.w};
#pragma unroll
            for (int i = 0; i < 4; i++)
#pragma unroll
                for (int j = 0; j < 4; j++)
                    acc[i][j] += ar[i] * wr[j];
        }

        // stash prefetched slice into the other buffer
        const int nb = buf ^ 1;
        As[nb][lk + 0][lrow] = av.x; As[nb][lk + 1][lrow] = av.y;
        As[nb][lk + 2][lrow] = av.z; As[nb][lk + 3][lrow] = av.w;
        Ws[nb][lk + 0][lrow] = wv.x; Ws[nb][lk + 1][lrow] = wv.y;
        Ws[nb][lk + 2][lrow] = wv.z; Ws[nb][lk + 3][lrow] = wv.w;
        __syncthreads();
        buf = nb;
    }

    // ---- epilogue slice ----
#pragma unroll
    for (int kk = 0; kk < BK; kk++) {
        float4 a = *(const float4*)&As[buf][kk][ty << 2];
        float4 w = *(const float4*)&Ws[buf][kk][tx << 2];
        float ar[4] = {a.x, a.y, a.z, a.w};
        float wr[4] = {w.x, w.y, w.z, w.w};
#pragma unroll
        for (int i = 0; i < 4; i++)
#pragma unroll
            for (int j = 0; j < 4; j++)
                acc[i][j] += ar[i] * wr[j];
    }

#pragma unroll
    for (int i = 0; i < 4; i++) {
        const int m = bm + (ty << 2) + i;
#pragma unroll
        for (int j = 0; j < 4; j++) {
            const int n = bn + (tx << 2) + j;
            float v = acc[i][j];
            if (MODE == 1) v += extra[(size_t)m * N + n];
            if (MODE == 2) v += extra[n];
            if (MODE != 2) v = v > 0.f ? v : 0.f;
            C[(size_t)m * N + n] = v;
            if (MODE == 1 && C2 != nullptr) C2[(size_t)m * N + n] = v;
        }
    }
}

// Pack [act_sequence[:,t,:], latent] into rows r = t*B + b, width 192.
__global__ void pack_k(const float* __restrict__ act,
                       const float* __restrict__ lat,
                       float* __restrict__ out)
{
    int idx = blockIdx.x * blockDim.x + threadIdx.x;
    if (idx >= Tt * Bsz * KAP) return;
    int k = idx % KAP;
    int r = idx / KAP;
    int b = r % Bsz;
    int t = r / Bsz;
    float v = (k < Asz) ? act[((size_t)b * Tt + t) * Asz + k]
                        : lat[(size_t)b * Psz + (k - Asz)];
    out[idx] = v;
}

// fc1_eff[n,k] = fc1_W[n,k] + fc1_W[n, S+k]   (exploits combined = [h, h])
__global__ void eff_k(const float* __restrict__ w1, float* __restrict__ out)
{
    int idx = blockIdx.x * blockDim.x + threadIdx.x;
    if (idx >= Ssz * Ssz) return;
    int n = idx / Ssz, k = idx % Ssz;
    out[idx] = w1[(size_t)n * 2 * Ssz + k] + w1[(size_t)n * 2 * Ssz + Ssz + k];
}

// LSTM gates + cell/hidden update + per-row reward dot. One block per batch row.
__global__ __launch_bounds__(256) void gates_k(
    const float* __restrict__ cc,
    float* __restrict__ c,
    float* __restrict__ hn,
    float* __restrict__ preds,
    float* __restrict__ rew,
    const float* __restrict__ rW,
    const float* __restrict__ rb)
{
    const int b   = blockIdx.x;
    const int tid = threadIdx.x;
    const float* row = cc + (size_t)b * S4;
    float partial = 0.f;

    for (int s = tid; s < Ssz; s += 256) {
        float ig = 1.f / (1.f + expf(-row[s]));
        float fg = 1.f / (1.f + expf(-row[Ssz + s]));
        float og = 1.f / (1.f + expf(-row[2 * Ssz + s]));
        float gg = tanhf(row[3 * Ssz + s]);
        float cv = fg * c[(size_t)b * Ssz + s] + ig * gg;
        float hv = og * tanhf(cv);
        c[(size_t)b * Ssz + s]     = cv;
        hn[(size_t)b * Ssz + s]    = hv;
        preds[(size_t)b * Ssz + s] = hv;
        partial += hv * rW[s];
    }

    __shared__ float red[256];
    red[tid] = partial;
    __syncthreads();
#pragma unroll
    for (int st = 128; st > 0; st >>= 1) {
        if (tid < st) red[tid] += red[tid + st];
        __syncthreads();
    }
    if (tid == 0) rew[b] = red[0] + rb[0];
}

extern "C" void kernel_launch(void* const* d_in, const int* in_sizes, int n_in,
                              void* d_out, int out_size)
{
    (void)in_sizes; (void)n_in; (void)out_size;

    const float* state = (const float*)d_in[0];   // [B, S]
    const float* act   = (const float*)d_in[1];   // [B, T, A]
    const float* lat   = (const float*)d_in[2];   // [B, P]
    const float* fcW   = (const float*)d_in[3];   // [S, S+A+P]
    const float* fcb   = (const float*)d_in[4];   // [S]
    const float* fc1W  = (const float*)d_in[5];   // [S, 2S]
    const float* fc2W  = (const float*)d_in[6];   // [S, S]
    const float* WW    = (const float*)d_in[7];   // [4S, S]
    const float* rW    = (const float*)d_in[8];   // [1, S]
    const float* rb    = (const float*)d_in[9];   // [1]

    float* out   = (float*)d_out;
    float* preds = out;                                  // [T*B, S]
    float* rews  = out + (size_t)Tt * Bsz * Ssz;         // [T*B, 1]

    float *h, *c, *x1, *x2, *cc, *hn, *base, *eff, *al;
    cudaGetSymbolAddress((void**)&h,    g_h);
    cudaGetSymbolAddress((void**)&c,    g_c);
    cudaGetSymbolAddress((void**)&x1,   g_x1);
    cudaGetSymbolAddress((void**)&x2,   g_x2);
    cudaGetSymbolAddress((void**)&cc,   g_cc);
    cudaGetSymbolAddress((void**)&hn,   g_hn);
    cudaGetSymbolAddress((void**)&base, g_base);
    cudaGetSymbolAddress((void**)&eff,  g_eff);
    cudaGetSymbolAddress((void**)&al,   g_al);

    cudaStream_t st = cudaStreamPerThread;

    // 1) pack act/latent rows, build fc1_eff
    pack_k<<<(Tt * Bsz * KAP + 255) / 256, 256, 0, st>>>(act, lat, al);
    eff_k<<<(Ssz * Ssz + 255) / 256, 256, 0, st>>>(fc1W, eff);

    // 2) base[t*B+b, :] = [act_t, latent] @ fc_W[:, S:].T + fc_b   (all steps at once)
    {
        dim3 g(Ssz / BN, (Tt * Bsz) / BM);
        gemm_k<2><<<g, 256, 0, st>>>(al, KAP, fcW + Ssz, SAP, base, fcb, nullptr,
                                     Ssz, KAP);
    }

    dim3 gm(Ssz / BN, Bsz / BM);   // (32, 4)  — M=256, N=2048 GEMMs
    dim3 g3(S4 / BN, Bsz / BM);    // (128, 4) — the 4S-wide gate GEMM

    // 3) init: hidden = cell = relu(state @ fc_W[:, :S].T + base[0])
    gemm_k<1><<<gm, 256, 0, st>>>(state, Ssz, fcW, SAP, h, base, c, Ssz, Ssz);

    // 4) recurrence
    for (int t = 0; t < Tt; t++) {
        gemm_k<0><<<gm, 256, 0, st>>>(h,  Ssz, eff,  Ssz, x1, nullptr, nullptr, Ssz, Ssz);
        gemm_k<0><<<gm, 256, 0, st>>>(x1, Ssz, fc2W, Ssz, x2, nullptr, nullptr, Ssz, Ssz);
        gemm_k<0><<<g3, 256, 0, st>>>(x2, Ssz, WW,   Ssz, cc, nullptr, nullptr, S4,  Ssz);
        gates_k<<<Bsz, 256, 0, st>>>(cc, c, hn,
                                     preds + (size_t)t * Bsz * Ssz,
                                     rews + (size_t)t * Bsz, rW, rb);
        if (t < Tt - 1) {
            // next carry: h = relu(h_next @ fc_W[:, :S].T + base[t])
            gemm_k<1><<<gm, 256, 0, st>>>(hn, Ssz, fcW, SAP, h,
                                          base + (size_t)t * Bsz * Ssz, nullptr,
                                          Ssz, Ssz);
        }
    }
}

// round 7
// speedup vs baseline: 1.0421x; 1.0421x over previous
#include <cuda_runtime.h>
#include <math.h>

// Problem dims
#define Bsz 256
#define Tt  32
#define Ssz 2048
#define Asz 64
#define Psz 128
#define KAP 192          // A + P
#define SAP 2240         // S + A + P  (fc_W row stride)
#define S4  8192         // 4*S

// ---- scratch (device globals: allocation-free rule) ----
__device__ float g_h   [Bsz * Ssz];       // carry hidden
__device__ float g_c   [Bsz * Ssz];       // carry cell
__device__ float g_x1  [Bsz * Ssz];
__device__ float g_x2  [Bsz * Ssz];
__device__ float g_cc  [Bsz * S4];
__device__ float g_hn  [Bsz * Ssz];       // h_next
__device__ float g_base[Tt * Bsz * Ssz];  // per-step act/latent/bias contribution of fc
__device__ float g_eff [Ssz * Ssz];       // fc1_W[:, :S] + fc1_W[:, S:]
__device__ float g_al  [Tt * Bsz * KAP];  // packed [act_t, latent] rows

// ---------------------------------------------------------------------------
// Double-buffered tiled fp32 GEMM:  C[m,n] = epilogue( sum_k A[m,k] * W[n,k] )
// A: [M,K] row-major (lda), W: [N,K] row-major (ldw), C: [M,N] (ldc == N)
// MODE 0: relu(acc)
// MODE 1: relu(acc + extra[m*N + n]); optional duplicate store to C2
// MODE 2: acc + extra[n]              (bias, no relu)
// Requires M%64==0, N%64==0, K%16==0 (all shapes here satisfy this).
// ---------------------------------------------------------------------------
#define BM 64
#define BN 64
#define BK 16

template <int MODE>
__global__ __launch_bounds__(256, 2) void gemm_k(
    const float* __restrict__ A, int lda,
    const float* __restrict__ W, int ldw,
    float* __restrict__ C,
    const float* __restrict__ extra,
    float* __restrict__ C2,
    int N, int K)
{
    __shared__ float As[2][BK][BM + 8];
    __shared__ float Ws[2][BK][BN + 8];

    const int bm  = blockIdx.y * BM;
    const int bn  = blockIdx.x * BN;
    const int tid = threadIdx.x;

    // loader mapping: 256 threads, one float4 of A-tile and one of W-tile each
    const int lrow = tid >> 2;          // 0..63
    const int lk   = (tid & 3) << 2;    // 0,4,8,12

    // compute mapping: 16x16 threads, 4x4 outputs each
    const int ty = tid >> 4;
    const int tx = tid & 15;

    const float* Ap = A + (size_t)(bm + lrow) * lda + lk;
    const float* Wp = W + (size_t)(bn + lrow) * ldw + lk;

    float acc[4][4] = {};

    // ---- prologue: load K-slice 0 into buffer 0 ----
    {
        float4 av = *(const float4*)(Ap);
        float4 wv = *(const float4*)(Wp);
        As[0][lk + 0][lrow] = av.x; As[0][lk + 1][lrow] = av.y;
        As[0][lk + 2][lrow] = av.z; As[0][lk + 3][lrow] = av.w;
        Ws[0][lk + 0][lrow] = wv.x; Ws[0][lk + 1][lrow] = wv.y;
        Ws[0][lk + 2][lrow] = wv.z; Ws[0][lk + 3][lrow] = wv.w;
    }
    __syncthreads();

    int buf = 0;
    for (int k0 = BK; k0 < K; k0 += BK) {
        // prefetch next slice into registers (overlaps with FMAs below)
        float4 av = *(const float4*)(Ap + k0);
        float4 wv = *(const float4*)(Wp + k0);

        // compute on current buffer
#pragma unroll
        for (int kk = 0; kk < BK; kk++) {
            float4 a = *(const float4*)&As[buf][kk][ty << 2];
            float4 w = *(const float4*)&Ws[buf][kk][tx << 2];
            float ar[4] = {a.x, a.y, a.z, a.w};
            float wr[4] = {w.x, w.y, w.z, w.w};
#pragma unroll
            for (int i = 0; i < 4; i++)
#pragma unroll
                for (int j = 0; j < 4; j++)
                    acc[i][j] += ar[i] * wr[j];
        }

        // stash prefetched slice into the other buffer
        const int nb = buf ^ 1;
        As[nb][lk + 0][lrow] = av.x; As[nb][lk + 1][lrow] = av.y;
        As[nb][lk + 2][lrow] = av.z; As[nb][lk + 3][lrow] = av.w;
        Ws[nb][lk + 0][lrow] = wv.x; Ws[nb][lk + 1][lrow] = wv.y;
        Ws[nb][lk + 2][lrow] = wv.z; Ws[nb][lk + 3][lrow] = wv.w;
        __syncthreads();
        buf = nb;
    }

    // ---- epilogue slice ----
#pragma unroll
    for (int kk = 0; kk < BK; kk++) {
        float4 a = *(const float4*)&As[buf][kk][ty << 2];
        float4 w = *(const float4*)&Ws[buf][kk][tx << 2];
        float ar[4] = {a.x, a.y, a.z, a.w};
        float wr[4] = {w.x, w.y, w.z, w.w};
#pragma unroll
        for (int i = 0; i < 4; i++)
#pragma unroll
            for (int j = 0; j < 4; j++)
                acc[i][j] += ar[i] * wr[j];
    }

#pragma unroll
    for (int i = 0; i < 4; i++) {
        const int m = bm + (ty << 2) + i;
#pragma unroll
        for (int j = 0; j < 4; j++) {
            const int n = bn + (tx << 2) + j;
            float v = acc[i][j];
            if (MODE == 1) v += extra[(size_t)m * N + n];
            if (MODE == 2) v += extra[n];
            if (MODE != 2) v = v > 0.f ? v : 0.f;
            C[(size_t)m * N + n] = v;
            if (MODE == 1 && C2 != nullptr) C2[(size_t)m * N + n] = v;
        }
    }
}

// Pack [act_sequence[:,t,:], latent] into rows r = t*B + b, width 192.
__global__ void pack_k(const float* __restrict__ act,
                       const float* __restrict__ lat,
                       float* __restrict__ out)
{
    int idx = blockIdx.x * blockDim.x + threadIdx.x;
    if (idx >= Tt * Bsz * KAP) return;
    int k = idx % KAP;
    int r = idx / KAP;
    int b = r % Bsz;
    int t = r / Bsz;
    float v = (k < Asz) ? act[((size_t)b * Tt + t) * Asz + k]
                        : lat[(size_t)b * Psz + (k - Asz)];
    out[idx] = v;
}

// fc1_eff[n,k] = fc1_W[n,k] + fc1_W[n, S+k]   (exploits combined = [h, h])
__global__ void eff_k(const float* __restrict__ w1, float* __restrict__ out)
{
    int idx = blockIdx.x * blockDim.x + threadIdx.x;
    if (idx >= Ssz * Ssz) return;
    int n = idx / Ssz, k = idx % Ssz;
    out[idx] = w1[(size_t)n * 2 * Ssz + k] + w1[(size_t)n * 2 * Ssz + Ssz + k];
}

// LSTM gates + cell/hidden update + per-row reward dot. One block per batch row.
__global__ __launch_bounds__(256) void gates_k(
    const float* __restrict__ cc,
    float* __restrict__ c,
    float* __restrict__ hn,
    float* __restrict__ preds,
    float* __restrict__ rew,
    const float* __restrict__ rW,
    const float* __restrict__ rb)
{
    const int b   = blockIdx.x;
    const int tid = threadIdx.x;
    const float* row = cc + (size_t)b * S4;
    float partial = 0.f;

    for (int s = tid; s < Ssz; s += 256) {
        float ig = 1.f / (1.f + expf(-row[s]));
        float fg = 1.f / (1.f + expf(-row[Ssz + s]));
        float og = 1.f / (1.f + expf(-row[2 * Ssz + s]));
        float gg = tanhf(row[3 * Ssz + s]);
        float cv = fg * c[(size_t)b * Ssz + s] + ig * gg;
        float hv = og * tanhf(cv);
        c[(size_t)b * Ssz + s]     = cv;
        hn[(size_t)b * Ssz + s]    = hv;
        preds[(size_t)b * Ssz + s] = hv;
        partial += hv * rW[s];
    }

    __shared__ float red[256];
    red[tid] = partial;
    __syncthreads();
#pragma unroll
    for (int st = 128; st > 0; st >>= 1) {
        if (tid < st) red[tid] += red[tid + st];
        __syncthreads();
    }
    if (tid == 0) rew[b] = red[0] + rb[0];
}

extern "C" void kernel_launch(void* const* d_in, const int* in_sizes, int n_in,
                              void* d_out, int out_size)
{
    (void)in_sizes; (void)n_in; (void)out_size;

    const float* state = (const float*)d_in[0];   // [B, S]
    const float* act   = (const float*)d_in[1];   // [B, T, A]
    const float* lat   = (const float*)d_in[2];   // [B, P]
    const float* fcW   = (const float*)d_in[3];   // [S, S+A+P]
    const float* fcb   = (const float*)d_in[4];   // [S]
    const float* fc1W  = (const float*)d_in[5];   // [S, 2S]
    const float* fc2W  = (const float*)d_in[6];   // [S, S]
    const float* WW    = (const float*)d_in[7];   // [4S, S]
    const float* rW    = (const float*)d_in[8];   // [1, S]
    const float* rb    = (const float*)d_in[9];   // [1]

    float* out   = (float*)d_out;
    float* preds = out;                                  // [T*B, S]
    float* rews  = out + (size_t)Tt * Bsz * Ssz;         // [T*B, 1]

    float *h, *c, *x1, *x2, *cc, *hn, *base, *eff, *al;
    cudaGetSymbolAddress((void**)&h,    g_h);
    cudaGetSymbolAddress((void**)&c,    g_c);
    cudaGetSymbolAddress((void**)&x1,   g_x1);
    cudaGetSymbolAddress((void**)&x2,   g_x2);
    cudaGetSymbolAddress((void**)&cc,   g_cc);
    cudaGetSymbolAddress((void**)&hn,   g_hn);
    cudaGetSymbolAddress((void**)&base, g_base);
    cudaGetSymbolAddress((void**)&eff,  g_eff);
    cudaGetSymbolAddress((void**)&al,   g_al);

    cudaStream_t st = cudaStreamPerThread;

    // 1) pack act/latent rows, build fc1_eff
    pack_k<<<(Tt * Bsz * KAP + 255) / 256, 256, 0, st>>>(act, lat, al);
    eff_k<<<(Ssz * Ssz + 255) / 256, 256, 0, st>>>(fc1W, eff);

    // 2) base[t*B+b, :] = [act_t, latent] @ fc_W[:, S:].T + fc_b   (all steps at once)
    {
        dim3 g(Ssz / BN, (Tt * Bsz) / BM);
        gemm_k<2><<<g, 256, 0, st>>>(al, KAP, fcW + Ssz, SAP, base, fcb, nullptr,
                                     Ssz, KAP);
    }

    dim3 gm(Ssz / BN, Bsz / BM);   // (32, 4)  — M=256, N=2048 GEMMs
    dim3 g3(S4 / BN, Bsz / BM);    // (128, 4) — the 4S-wide gate GEMM

    // 3) init: hidden = cell = relu(state @ fc_W[:, :S].T + base[0])
    gemm_k<1><<<gm, 256, 0, st>>>(state, Ssz, fcW, SAP, h, base, c, Ssz, Ssz);

    // 4) recurrence
    for (int t = 0; t < Tt; t++) {
        gemm_k<0><<<gm, 256, 0, st>>>(h,  Ssz, eff,  Ssz, x1, nullptr, nullptr, Ssz, Ssz);
        gemm_k<0><<<gm, 256, 0, st>>>(x1, Ssz, fc2W, Ssz, x2, nullptr, nullptr, Ssz, Ssz);
        gemm_k<0><<<g3, 256, 0, st>>>(x2, Ssz, WW,   Ssz, cc, nullptr, nullptr, S4,  Ssz);
        gates_k<<<Bsz, 256, 0, st>>>(cc, c, hn,
                                     preds + (size_t)t * Bsz * Ssz,
                                     rews + (size_t)t * Bsz, rW, rb);
        if (t < Tt - 1) {
            // next carry: h = relu(h_next @ fc_W[:, :S].T + base[t])
            gemm_k<1><<<gm, 256, 0, st>>>(hn, Ssz, fcW, SAP, h,
                                          base + (size_t)t * Bsz * Ssz, nullptr,
                                          Ssz, Ssz);
        }
    }
}